// round 14
// baseline (speedup 1.0000x reference)
#include <cuda_runtime.h>
#include <cuda_fp16.h>
#include <cstdint>

#define N_NODES 8192
#define IN_DIM  256
#define OUT_DIM 128
#define NCOLS   144     // 128 out cols + g col (idx 128) + 15 pad
#define CH_K    64      // K per chunk (fp16), 128B rows
#define SPLITS  4

// ---------------- device scratch (zero-initialized at module load) ---------
__device__ __align__(16) __half Pt_f16[NCOLS * N_NODES];      // [n][k], rows>128 stay 0
__device__ __align__(16) float part_buf[SPLITS * N_NODES * NCOLS];
__device__ int tile_cnt[64];                                   // self-resetting

// ---------------- helpers ---------------------------------------------------
__device__ __forceinline__ uint32_t smem_u32(const void* p) {
    uint32_t a;
    asm("{ .reg .u64 t; cvta.to.shared.u64 t, %1; cvt.u32.u64 %0, t; }"
        : "=r"(a) : "l"(p));
    return a;
}
// SW128 swizzle for [rows][64 halves] tiles (128B rows, 16B chunks 0..7)
__device__ __forceinline__ uint32_t swz128(int row, int chunk) {
    return (uint32_t)(row * 128 + ((chunk ^ (row & 7)) << 4));
}

#define LDSM_X4(r, addr) \
    asm volatile("ldmatrix.sync.aligned.m8n8.x4.shared.b16 {%0,%1,%2,%3}, [%4];" \
        : "=r"((r)[0]), "=r"((r)[1]), "=r"((r)[2]), "=r"((r)[3]) : "r"(addr))
#define LDSM_X2(r0, r1, addr) \
    asm volatile("ldmatrix.sync.aligned.m8n8.x2.shared.b16 {%0,%1}, [%2];" \
        : "=r"(r0), "=r"(r1) : "r"(addr))
#define MMA16816(c, a, b0, b1) \
    asm volatile("mma.sync.aligned.m16n8k16.row.col.f32.f16.f16.f32 " \
        "{%0,%1,%2,%3},{%4,%5,%6,%7},{%8,%9},{%0,%1,%2,%3};" \
        : "+f"((c)[0]), "+f"((c)[1]), "+f"((c)[2]), "+f"((c)[3]) \
        : "r"((a)[0]), "r"((a)[1]), "r"((a)[2]), "r"((a)[3]), "r"(b0), "r"(b1))
#define CP_ASYNC16(daddr, gptr) \
    asm volatile("cp.async.cg.shared.global [%0], [%1], 16;" \
        :: "r"(daddr), "l"(gptr) : "memory")
#define CP_COMMIT() asm volatile("cp.async.commit_group;" ::: "memory")
#define CP_WAIT0()  asm volatile("cp.async.wait_group 0;" ::: "memory")
#define CP_WAIT1()  asm volatile("cp.async.wait_group 1;" ::: "memory")

// ---------------------------------------------------------------------------
// Phase 1 (R13 4x8 tile + double-buffered k0 loop):
// Wh = X @ W^T, e = relu(Wh)@a_w, g = exp(e) (no max shift needed in fp16).
// Writes Pt_f16[c][node] = fp16(g*Wh[node][c]), row 128 = g.
// 128 blocks x 64 nodes, 256 threads (16tx x 16ty), tile 4 rows x 8 cols.
// ---------------------------------------------------------------------------
__global__ __launch_bounds__(256)
void gat_phase1(const float* __restrict__ X,
                const float* __restrict__ W,
                const float* __restrict__ a_w)
{
    // [Xs0 8704][Xs1 8704][Ws0 16896][Ws1 16896] = 51200 B
    __shared__ __align__(16) unsigned char sraw[51200];
    __shared__ float aw_s[OUT_DIM];

    const int t  = threadIdx.x;
    const int tx = t & 15;
    const int ty = t >> 4;
    const int node0 = blockIdx.x * 64;

    if (t < OUT_DIM) aw_s[t] = a_w[t];

    float acc[4][8];
    #pragma unroll
    for (int r = 0; r < 4; r++)
        #pragma unroll
        for (int j = 0; j < 8; j++) acc[r][j] = 0.0f;

    // prefetch registers
    float4 xv[2], wv[4];
    const int xrow = t >> 2, xq = t & 3;     // X: 64 rows, 2 float4 each
    const int wq = t & 7, wcb = t >> 3;      // W: transposed loads

    auto LDGX = [&](int k0) {
        #pragma unroll
        for (int it = 0; it < 2; it++) {
            const int f4 = xq + 4 * it;
            xv[it] = *reinterpret_cast<const float4*>(
                &X[(node0 + xrow) * IN_DIM + k0 + 4 * f4]);
        }
    };
    auto LDGW = [&](int k0) {
        #pragma unroll
        for (int it = 0; it < 4; it++) {
            const int c = wcb + 32 * it;
            wv[it] = *reinterpret_cast<const float4*>(&W[c * IN_DIM + k0 + 4 * wq]);
        }
    };
    auto STSX = [&](int b) {
        float* Xb = (float*)(sraw + b * 8704);
        #pragma unroll
        for (int it = 0; it < 2; it++) {
            const int f4 = xq + 4 * it;
            Xb[(4*f4+0)*68 + xrow] = xv[it].x; Xb[(4*f4+1)*68 + xrow] = xv[it].y;
            Xb[(4*f4+2)*68 + xrow] = xv[it].z; Xb[(4*f4+3)*68 + xrow] = xv[it].w;
        }
    };
    auto STSW = [&](int b) {
        float* Wb = (float*)(sraw + 17408 + b * 16896);
        #pragma unroll
        for (int it = 0; it < 4; it++) {
            const int c = wcb + 32 * it;
            Wb[(4*wq+0)*132 + c] = wv[it].x; Wb[(4*wq+1)*132 + c] = wv[it].y;
            Wb[(4*wq+2)*132 + c] = wv[it].z; Wb[(4*wq+3)*132 + c] = wv[it].w;
        }
    };

    LDGX(0); LDGW(0); STSX(0); STSW(0);
    __syncthreads();

    for (int i = 0; i < 8; i++) {
        const int b = i & 1;
        if (i < 7) { LDGX(32 * (i + 1)); LDGW(32 * (i + 1)); }

        const float* Xb = (const float*)(sraw + b * 8704);
        const float* Wb = (const float*)(sraw + 17408 + b * 16896);
        #pragma unroll
        for (int k = 0; k < 32; k++) {
            float4 av = *reinterpret_cast<const float4*>(&Xb[k * 68 + 4 * ty]);
            float4 b0 = *reinterpret_cast<const float4*>(&Wb[k * 132 + 8 * tx]);
            float4 b1 = *reinterpret_cast<const float4*>(&Wb[k * 132 + 8 * tx + 4]);
            float a4[4] = {av.x, av.y, av.z, av.w};
            float bb[8] = {b0.x, b0.y, b0.z, b0.w, b1.x, b1.y, b1.z, b1.w};
            #pragma unroll
            for (int r = 0; r < 4; r++)
                #pragma unroll
                for (int j = 0; j < 8; j++)
                    acc[r][j] = fmaf(a4[r], bb[j], acc[r][j]);
        }
        if (i < 7) { STSX(b ^ 1); STSW(b ^ 1); }
        __syncthreads();
    }

    // g per row (reduce e over the 16 tx lanes; warp = 16 tx x 2 ty)
    float g[4];
    #pragma unroll
    for (int r = 0; r < 4; r++) {
        float ep = 0.0f;
        #pragma unroll
        for (int j = 0; j < 8; j++)
            ep = fmaf(fmaxf(acc[r][j], 0.0f), aw_s[8 * tx + j], ep);
        #pragma unroll
        for (int m = 8; m >= 1; m >>= 1)
            ep += __shfl_xor_sync(0xffffffffu, ep, m, 16);
        g[r] = expf(ep);
    }

    // transpose + fp16 through smem staging [129][72] (144B rows, 8B-aligned)
    __half* th = (__half*)sraw;   // 129*72*2 = 18576 B (reuses buffers)
    #pragma unroll
    for (int j = 0; j < 8; j++) {
        const int c = 8 * tx + j;
        __half2 o0 = __floats2half2_rn(g[0] * acc[0][j], g[1] * acc[1][j]);
        __half2 o1 = __floats2half2_rn(g[2] * acc[2][j], g[3] * acc[3][j]);
        uint2 u;
        u.x = *reinterpret_cast<unsigned*>(&o0);
        u.y = *reinterpret_cast<unsigned*>(&o1);
        *reinterpret_cast<uint2*>(&th[c * 72 + 4 * ty]) = u;
    }
    if (tx == 0) {
        __half2 o0 = __floats2half2_rn(g[0], g[1]);
        __half2 o1 = __floats2half2_rn(g[2], g[3]);
        uint2 u;
        u.x = *reinterpret_cast<unsigned*>(&o0);
        u.y = *reinterpret_cast<unsigned*>(&o1);
        *reinterpret_cast<uint2*>(&th[128 * 72 + 4 * ty]) = u;
    }
    __syncthreads();
    {   // write out: 129 rows x 64 nodes (128B per row, one warp per row)
        const int wid = t >> 5, lid = t & 31;
        for (int c = wid; c < 129; c += 8) {
            unsigned v = *reinterpret_cast<unsigned*>(&th[c * 72 + 2 * lid]);
            *reinterpret_cast<unsigned*>(
                &Pt_f16[(size_t)c * N_NODES + node0 + 2 * lid]) = v;
        }
    }
}

// ---------------------------------------------------------------------------
// Phase 2: fp16 HMMA GEMM + fused finalize. CH_K=64 (32 barriers, was 64).
// CTA: M=128, N=144; 256 threads = 8 warps (4m x 2n, m32 x n72).
// 3-stage pipeline, 256 CTAs (64 M-tiles x 4 K-splits), 2 CTAs/SM.
// A loaded in two 16-reg halves interleaved between compute halves.
// ---------------------------------------------------------------------------
#define STG_BYTES 34816     // A 16384 + B 18432
#define B_OFF     16384
#define PH2_SMEM  (3 * STG_BYTES)

__global__ __launch_bounds__(256, 2)
void gat_phase2(const float* __restrict__ A, float* __restrict__ out)
{
    extern __shared__ unsigned char sm[];
    const uint32_t sbase0 = smem_u32(sm);
    __shared__ int s_last;

    const int t     = threadIdx.x;
    const int lane  = t & 31;
    const int wid   = t >> 5;
    const int tile  = blockIdx.x & 63;
    const int split = blockIdx.x >> 6;
    const int r0    = tile * 128;
    const int kbase = split * (N_NODES / SPLITS);
    const int NCH   = (N_NODES / SPLITS) / CH_K;   // 32

    const int m0 = (wid & 3) * 32;
    const int n0 = (wid >> 2) * 72;

    float C0[9][4], C1[9][4];
    #pragma unroll
    for (int j = 0; j < 9; j++)
        #pragma unroll
        for (int q = 0; q < 4; q++) { C0[j][q] = 0.0f; C1[j][q] = 0.0f; }

    float4 av[4];                  // one 16-float half of this thread's 32
    const int ar = t >> 1;         // row 0..127
    const int ac = t & 1;          // 16-col group within a 32-col half

    auto LDG_A = [&](int i, int p) {
        const float4* src = reinterpret_cast<const float4*>(
            &A[(size_t)(r0 + ar) * N_NODES + kbase + i * CH_K + p * 32 + ac * 16]);
        av[0] = src[0]; av[1] = src[1]; av[2] = src[2]; av[3] = src[3];
    };
    auto STS_A = [&](int stg, int p) {
        const int bc = 4 * p + 2 * ac;
        #pragma unroll
        for (int j = 0; j < 2; j++) {
            __half2 h0 = __floats2half2_rn(av[2*j].x, av[2*j].y);
            __half2 h1 = __floats2half2_rn(av[2*j].z, av[2*j].w);
            __half2 h2 = __floats2half2_rn(av[2*j+1].x, av[2*j+1].y);
            __half2 h3 = __floats2half2_rn(av[2*j+1].z, av[2*j+1].w);
            uint4 u;
            u.x = *reinterpret_cast<unsigned*>(&h0);
            u.y = *reinterpret_cast<unsigned*>(&h1);
            u.z = *reinterpret_cast<unsigned*>(&h2);
            u.w = *reinterpret_cast<unsigned*>(&h3);
            *reinterpret_cast<uint4*>(
                sm + stg * STG_BYTES + swz128(ar, bc + j)) = u;
        }
    };
    auto LOAD_B = [&](int i, int stg) {
        const uint32_t db = sbase0 + stg * STG_BYTES + B_OFF;
        #pragma unroll
        for (int it = 0; it < 5; it++) {
            int idx = t + it * 256;
            if (idx < 1152) {
                int n = idx >> 3, c = idx & 7;
                const __half* g = Pt_f16 + (size_t)n * N_NODES
                                + kbase + i * CH_K + c * 8;
                CP_ASYNC16(db + swz128(n, c), g);
            }
        }
    };
    auto COMPUTE_H = [&](uint32_t ab, uint32_t bb, int h) {
        uint32_t a0[4], a1[4];
        {
            const int kc = 2 * h + (lane >> 4);
            LDSM_X4(a0, ab + swz128(m0 + (lane & 15), kc));
            LDSM_X4(a1, ab + swz128(m0 + 16 + (lane & 15), kc));
        }
        const int kcb = 2 * h + ((lane >> 3) & 1);
        #pragma unroll
        for (int jg = 0; jg < 4; jg++) {
            int n = n0 + jg * 16 + ((lane >> 4) << 3) + (lane & 7);
            uint32_t b[4];
            LDSM_X4(b, bb + swz128(n, kcb));
            MMA16816(C0[2*jg],   a0, b[0], b[1]);
            MMA16816(C0[2*jg+1], a0, b[2], b[3]);
            MMA16816(C1[2*jg],   a1, b[0], b[1]);
            MMA16816(C1[2*jg+1], a1, b[2], b[3]);
        }
        {
            int n = n0 + 64 + (lane & 7);
            uint32_t b0, b1;
            LDSM_X2(b0, b1, bb + swz128(n, kcb));
            MMA16816(C0[8], a0, b0, b1);
            MMA16816(C1[8], a1, b0, b1);
        }
    };

    // ---- prologue: fill stages 0 and 1 ----
    LDG_A(0, 0); STS_A(0, 0); LDG_A(0, 1); STS_A(0, 1);
    LOAD_B(0, 0); CP_COMMIT();
    LDG_A(1, 0); STS_A(1, 0); LDG_A(1, 1); STS_A(1, 1);
    LOAD_B(1, 1); CP_COMMIT();
    CP_WAIT1();
    __syncthreads();

    // ---- main loop: 32 iterations ----
    for (int i = 0; i < NCH; i++) {
        const int s = i % 3;
        const bool more2 = (i + 2 < NCH);
        const int s2 = (i + 2) % 3;
        const uint32_t ab = sbase0 + s * STG_BYTES;
        const uint32_t bb = ab + B_OFF;

        if (more2) { LOAD_B(i + 2, s2); CP_COMMIT(); LDG_A(i + 2, 0); }
        COMPUTE_H(ab, bb, 0);
        COMPUTE_H(ab, bb, 1);
        if (more2) { STS_A(s2, 0); LDG_A(i + 2, 1); }
        COMPUTE_H(ab, bb, 2);
        COMPUTE_H(ab, bb, 3);
        if (more2) { STS_A(s2, 1); CP_WAIT1(); }
        else if (i + 1 < NCH) { CP_WAIT0(); }
        __syncthreads();
    }

    // ---- epilogue: fp32 partials ----
    {
        const int rowb = r0 + m0 + (lane >> 2);
        const int col0 = n0 + (lane & 3) * 2;
        float* base = &part_buf[(size_t)split * N_NODES * NCOLS];
        #pragma unroll
        for (int j = 0; j < 9; j++) {
            const int col = col0 + j * 8;
            *reinterpret_cast<float2*>(&base[(size_t)rowb * NCOLS + col]) =
                make_float2(C0[j][0], C0[j][1]);
            *reinterpret_cast<float2*>(&base[(size_t)(rowb + 8) * NCOLS + col]) =
                make_float2(C0[j][2], C0[j][3]);
            *reinterpret_cast<float2*>(&base[(size_t)(rowb + 16) * NCOLS + col]) =
                make_float2(C1[j][0], C1[j][1]);
            *reinterpret_cast<float2*>(&base[(size_t)(rowb + 24) * NCOLS + col]) =
                make_float2(C1[j][2], C1[j][3]);
        }
    }

    // ---- fused finalize: last split-CTA per tile combines partials ----
    __threadfence();
    __syncthreads();
    if (t == 0)
        s_last = (atomicAdd(&tile_cnt[tile], 1) == SPLITS - 1);
    __syncthreads();
    if (s_last) {
        __threadfence();   // acquire: make peer partials visible
        const int row = r0 + (t >> 1);
        const int ch  = (t & 1) * 64;
        float den = 0.0f;
        #pragma unroll
        for (int s = 0; s < SPLITS; s++)
            den += part_buf[((size_t)s * N_NODES + row) * NCOLS + 128];
        const float inv = 1.0f / den;
        #pragma unroll
        for (int q = 0; q < 16; q++) {
            float4 acc4 = make_float4(0.f, 0.f, 0.f, 0.f);
            #pragma unroll
            for (int s = 0; s < SPLITS; s++) {
                float4 v = *reinterpret_cast<const float4*>(
                    &part_buf[((size_t)s * N_NODES + row) * NCOLS + ch + 4 * q]);
                acc4.x += v.x; acc4.y += v.y; acc4.z += v.z; acc4.w += v.w;
            }
            float4 o;
            o.x = fmaxf(acc4.x * inv, 0.0f);
            o.y = fmaxf(acc4.y * inv, 0.0f);
            o.z = fmaxf(acc4.z * inv, 0.0f);
            o.w = fmaxf(acc4.w * inv, 0.0f);
            *reinterpret_cast<float4*>(&out[(size_t)row * OUT_DIM + ch + 4 * q]) = o;
        }
        if (t == 0) tile_cnt[tile] = 0;   // self-reset for next graph replay
    }
}

// ---------------------------------------------------------------------------
extern "C" void kernel_launch(void* const* d_in, const int* in_sizes, int n_in,
                              void* d_out, int out_size)
{
    const float* X   = (const float*)d_in[0];
    const float* A   = (const float*)d_in[1];
    const float* W   = (const float*)d_in[2];
    const float* a_w = (const float*)d_in[3];
    float* out = (float*)d_out;

    cudaFuncSetAttribute(gat_phase2,
                         cudaFuncAttributeMaxDynamicSharedMemorySize, PH2_SMEM);

    gat_phase1<<<N_NODES / 64, 256>>>(X, W, a_w);
    gat_phase2<<<64 * SPLITS, 256, PH2_SMEM>>>(A, out);
}

// round 15
// speedup vs baseline: 1.0991x; 1.0991x over previous
#include <cuda_runtime.h>
#include <cuda_fp16.h>
#include <cstdint>

#define N_NODES 8192
#define IN_DIM  256
#define OUT_DIM 128
#define NCOLS   136     // 128 out cols + g col (idx 128) + 7 pad
#define CH_K    32      // K per chunk (fp16), 64B rows
#define SPLITS  4

// ---------------- device scratch (zero-initialized at module load) ---------
__device__ __align__(16) __half Pt_f16[NCOLS * N_NODES];      // [n][k], rows>128 stay 0
__device__ __align__(16) float part_buf[SPLITS * N_NODES * NCOLS];
__device__ int tile_cnt[64];                                   // self-resetting

// ---------------- helpers ---------------------------------------------------
__device__ __forceinline__ uint32_t smem_u32(const void* p) {
    uint32_t a;
    asm("{ .reg .u64 t; cvta.to.shared.u64 t, %1; cvt.u32.u64 %0, t; }"
        : "=r"(a) : "l"(p));
    return a;
}
// XOR-swizzled byte offset inside a [rows][32 halves] tile (64B rows)
__device__ __forceinline__ uint32_t swz(int row, int chunk) {
    return (uint32_t)(row * 64 + ((chunk ^ ((row >> 1) & 3)) << 4));
}

#define LDSM_X4(r, addr) \
    asm volatile("ldmatrix.sync.aligned.m8n8.x4.shared.b16 {%0,%1,%2,%3}, [%4];" \
        : "=r"((r)[0]), "=r"((r)[1]), "=r"((r)[2]), "=r"((r)[3]) : "r"(addr))
#define LDSM_X2(r0, r1, addr) \
    asm volatile("ldmatrix.sync.aligned.m8n8.x2.shared.b16 {%0,%1}, [%2];" \
        : "=r"(r0), "=r"(r1) : "r"(addr))
#define MMA16816(c, a, b0, b1) \
    asm volatile("mma.sync.aligned.m16n8k16.row.col.f32.f16.f16.f32 " \
        "{%0,%1,%2,%3},{%4,%5,%6,%7},{%8,%9},{%0,%1,%2,%3};" \
        : "+f"((c)[0]), "+f"((c)[1]), "+f"((c)[2]), "+f"((c)[3]) \
        : "r"((a)[0]), "r"((a)[1]), "r"((a)[2]), "r"((a)[3]), "r"(b0), "r"(b1))
#define CP_ASYNC16(daddr, gptr) \
    asm volatile("cp.async.cg.shared.global [%0], [%1], 16;" \
        :: "r"(daddr), "l"(gptr) : "memory")
#define CP_COMMIT() asm volatile("cp.async.commit_group;" ::: "memory")
#define CP_WAIT0()  asm volatile("cp.async.wait_group 0;" ::: "memory")
#define CP_WAIT1()  asm volatile("cp.async.wait_group 1;" ::: "memory")

// ---------------------------------------------------------------------------
// Phase 1 (R14-measured ~30us: 4x8 tile + double-buffered k0 loop):
// Wh = X @ W^T, e = relu(Wh)@a_w, g = exp(e) (no max shift needed in fp16).
// Writes Pt_f16[c][node] = fp16(g*Wh[node][c]), row 128 = g.
// 128 blocks x 64 nodes, 256 threads (16tx x 16ty), tile 4 rows x 8 cols.
// ---------------------------------------------------------------------------
__global__ __launch_bounds__(256)
void gat_phase1(const float* __restrict__ X,
                const float* __restrict__ W,
                const float* __restrict__ a_w)
{
    // [Xs0 8704][Xs1 8704][Ws0 16896][Ws1 16896] = 51200 B
    __shared__ __align__(16) unsigned char sraw[51200];
    __shared__ float aw_s[OUT_DIM];

    const int t  = threadIdx.x;
    const int tx = t & 15;
    const int ty = t >> 4;
    const int node0 = blockIdx.x * 64;

    if (t < OUT_DIM) aw_s[t] = a_w[t];

    float acc[4][8];
    #pragma unroll
    for (int r = 0; r < 4; r++)
        #pragma unroll
        for (int j = 0; j < 8; j++) acc[r][j] = 0.0f;

    float4 xv[2], wv[4];
    const int xrow = t >> 2, xq = t & 3;
    const int wq = t & 7, wcb = t >> 3;

    auto LDGX = [&](int k0) {
        #pragma unroll
        for (int it = 0; it < 2; it++) {
            const int f4 = xq + 4 * it;
            xv[it] = *reinterpret_cast<const float4*>(
                &X[(node0 + xrow) * IN_DIM + k0 + 4 * f4]);
        }
    };
    auto LDGW = [&](int k0) {
        #pragma unroll
        for (int it = 0; it < 4; it++) {
            const int c = wcb + 32 * it;
            wv[it] = *reinterpret_cast<const float4*>(&W[c * IN_DIM + k0 + 4 * wq]);
        }
    };
    auto STSX = [&](int b) {
        float* Xb = (float*)(sraw + b * 8704);
        #pragma unroll
        for (int it = 0; it < 2; it++) {
            const int f4 = xq + 4 * it;
            Xb[(4*f4+0)*68 + xrow] = xv[it].x; Xb[(4*f4+1)*68 + xrow] = xv[it].y;
            Xb[(4*f4+2)*68 + xrow] = xv[it].z; Xb[(4*f4+3)*68 + xrow] = xv[it].w;
        }
    };
    auto STSW = [&](int b) {
        float* Wb = (float*)(sraw + 17408 + b * 16896);
        #pragma unroll
        for (int it = 0; it < 4; it++) {
            const int c = wcb + 32 * it;
            Wb[(4*wq+0)*132 + c] = wv[it].x; Wb[(4*wq+1)*132 + c] = wv[it].y;
            Wb[(4*wq+2)*132 + c] = wv[it].z; Wb[(4*wq+3)*132 + c] = wv[it].w;
        }
    };

    LDGX(0); LDGW(0); STSX(0); STSW(0);
    __syncthreads();

    for (int i = 0; i < 8; i++) {
        const int b = i & 1;
        if (i < 7) { LDGX(32 * (i + 1)); LDGW(32 * (i + 1)); }

        const float* Xb = (const float*)(sraw + b * 8704);
        const float* Wb = (const float*)(sraw + 17408 + b * 16896);
        #pragma unroll
        for (int k = 0; k < 32; k++) {
            float4 av = *reinterpret_cast<const float4*>(&Xb[k * 68 + 4 * ty]);
            float4 b0 = *reinterpret_cast<const float4*>(&Wb[k * 132 + 8 * tx]);
            float4 b1 = *reinterpret_cast<const float4*>(&Wb[k * 132 + 8 * tx + 4]);
            float a4[4] = {av.x, av.y, av.z, av.w};
            float bb[8] = {b0.x, b0.y, b0.z, b0.w, b1.x, b1.y, b1.z, b1.w};
            #pragma unroll
            for (int r = 0; r < 4; r++)
                #pragma unroll
                for (int j = 0; j < 8; j++)
                    acc[r][j] = fmaf(a4[r], bb[j], acc[r][j]);
        }
        if (i < 7) { STSX(b ^ 1); STSW(b ^ 1); }
        __syncthreads();
    }

    // g per row (reduce e over the 16 tx lanes; warp = 16 tx x 2 ty)
    float g[4];
    #pragma unroll
    for (int r = 0; r < 4; r++) {
        float ep = 0.0f;
        #pragma unroll
        for (int j = 0; j < 8; j++)
            ep = fmaf(fmaxf(acc[r][j], 0.0f), aw_s[8 * tx + j], ep);
        #pragma unroll
        for (int m = 8; m >= 1; m >>= 1)
            ep += __shfl_xor_sync(0xffffffffu, ep, m, 16);
        g[r] = expf(ep);
    }

    // transpose + fp16 through smem staging [129][72] (144B rows, 8B-aligned)
    __half* th = (__half*)sraw;
    #pragma unroll
    for (int j = 0; j < 8; j++) {
        const int c = 8 * tx + j;
        __half2 o0 = __floats2half2_rn(g[0] * acc[0][j], g[1] * acc[1][j]);
        __half2 o1 = __floats2half2_rn(g[2] * acc[2][j], g[3] * acc[3][j]);
        uint2 u;
        u.x = *reinterpret_cast<unsigned*>(&o0);
        u.y = *reinterpret_cast<unsigned*>(&o1);
        *reinterpret_cast<uint2*>(&th[c * 72 + 4 * ty]) = u;
    }
    if (tx == 0) {
        __half2 o0 = __floats2half2_rn(g[0], g[1]);
        __half2 o1 = __floats2half2_rn(g[2], g[3]);
        uint2 u;
        u.x = *reinterpret_cast<unsigned*>(&o0);
        u.y = *reinterpret_cast<unsigned*>(&o1);
        *reinterpret_cast<uint2*>(&th[128 * 72 + 4 * ty]) = u;
    }
    __syncthreads();
    {   // write out: 129 rows x 64 nodes (128B per row, one warp per row)
        const int wid = t >> 5, lid = t & 31;
        for (int c = wid; c < 129; c += 8) {
            unsigned v = *reinterpret_cast<unsigned*>(&th[c * 72 + 2 * lid]);
            *reinterpret_cast<unsigned*>(
                &Pt_f16[(size_t)c * N_NODES + node0 + 2 * lid]) = v;
        }
    }
}

// ---------------------------------------------------------------------------
// Phase 2 (R13 structure, measured 116us, with N trimmed 144->136):
// CTA: M=128, N=136, K-chunk 32; 256 threads = 8 warps (4m x 2n).
// Warp n-group 0: cols 0..72 (4 jg + X2); group 1: cols 72..136 (4 jg).
// 3-stage pipeline, 256 CTAs (64 M-tiles x 4 K-splits), 2 CTAs/SM.
// ---------------------------------------------------------------------------
#define STG_BYTES 16896     // A 8192 + B 8704
#define B_OFF     8192
#define PH2_SMEM  (3 * STG_BYTES)

__global__ __launch_bounds__(256, 2)
void gat_phase2(const float* __restrict__ A, float* __restrict__ out)
{
    extern __shared__ unsigned char sm[];
    const uint32_t sbase0 = smem_u32(sm);
    __shared__ int s_last;

    const int t     = threadIdx.x;
    const int lane  = t & 31;
    const int wid   = t >> 5;
    const int tile  = blockIdx.x & 63;
    const int split = blockIdx.x >> 6;
    const int r0    = tile * 128;
    const int kbase = split * (N_NODES / SPLITS);
    const int NCH   = (N_NODES / SPLITS) / CH_K;   // 64

    const int m0 = (wid & 3) * 32;
    const int ng = wid >> 2;            // n-group: 0 -> cols 0..72, 1 -> 72..136
    const int n0 = ng * 72;

    float C0[9][4], C1[9][4];
    #pragma unroll
    for (int j = 0; j < 9; j++)
        #pragma unroll
        for (int q = 0; q < 4; q++) { C0[j][q] = 0.0f; C1[j][q] = 0.0f; }

    float4 av[4];
    const int ar = t >> 1;
    const int ac = t & 1;

    auto LDG_A = [&](int i) {
        const float4* src = reinterpret_cast<const float4*>(
            &A[(size_t)(r0 + ar) * N_NODES + kbase + i * CH_K + ac * 16]);
        av[0] = src[0]; av[1] = src[1]; av[2] = src[2]; av[3] = src[3];
    };
    auto STS_A = [&](int stg) {
        #pragma unroll
        for (int h = 0; h < 2; h++) {
            __half2 p0 = __floats2half2_rn(av[2*h].x, av[2*h].y);
            __half2 p1 = __floats2half2_rn(av[2*h].z, av[2*h].w);
            __half2 p2 = __floats2half2_rn(av[2*h+1].x, av[2*h+1].y);
            __half2 p3 = __floats2half2_rn(av[2*h+1].z, av[2*h+1].w);
            uint4 u;
            u.x = *reinterpret_cast<unsigned*>(&p0);
            u.y = *reinterpret_cast<unsigned*>(&p1);
            u.z = *reinterpret_cast<unsigned*>(&p2);
            u.w = *reinterpret_cast<unsigned*>(&p3);
            *reinterpret_cast<uint4*>(sm + stg * STG_BYTES + swz(ar, ac * 2 + h)) = u;
        }
    };
    auto LOAD_B = [&](int i, int stg) {
        const uint32_t db = sbase0 + stg * STG_BYTES + B_OFF;
        #pragma unroll
        for (int it = 0; it < 3; it++) {
            int idx = t + it * 256;
            if (idx < 4 * NCOLS) {     // 544
                int n = idx >> 2, c = idx & 3;
                const __half* g = Pt_f16 + (size_t)n * N_NODES
                                + kbase + i * CH_K + c * 8;
                CP_ASYNC16(db + swz(n, c), g);
            }
        }
    };

    // ---- prologue ----
    LDG_A(0); STS_A(0); LOAD_B(0, 0); CP_COMMIT();
    LDG_A(1); STS_A(1); LOAD_B(1, 1); CP_COMMIT();
    CP_WAIT1();
    __syncthreads();

    // ---- main loop ----
    for (int i = 0; i < NCH; i++) {
        const int s = i % 3;
        const bool more2 = (i + 2 < NCH);
        const int s2 = (i + 2) % 3;
        if (more2) {
            LDG_A(i + 2);
            LOAD_B(i + 2, s2);
            CP_COMMIT();
        }

        {
            const uint32_t ab = sbase0 + s * STG_BYTES;
            const uint32_t bb = ab + B_OFF;
            #pragma unroll
            for (int h = 0; h < 2; h++) {
                uint32_t a0[4], a1[4];
                {
                    const int kc = 2 * h + (lane >> 4);
                    LDSM_X4(a0, ab + swz(m0 + (lane & 15), kc));
                    LDSM_X4(a1, ab + swz(m0 + 16 + (lane & 15), kc));
                }
                const int kcb = 2 * h + ((lane >> 3) & 1);
                #pragma unroll
                for (int jg = 0; jg < 4; jg++) {
                    int n = n0 + jg * 16 + ((lane >> 4) << 3) + (lane & 7);
                    uint32_t b[4];
                    LDSM_X4(b, bb + swz(n, kcb));
                    MMA16816(C0[2*jg],   a0, b[0], b[1]);
                    MMA16816(C0[2*jg+1], a0, b[2], b[3]);
                    MMA16816(C1[2*jg],   a1, b[0], b[1]);
                    MMA16816(C1[2*jg+1], a1, b[2], b[3]);
                }
                if (ng == 0) {   // only group 0 owns the 64..72 tail columns
                    int n = 64 + (lane & 7);
                    uint32_t b0, b1;
                    LDSM_X2(b0, b1, bb + swz(n, kcb));
                    MMA16816(C0[8], a0, b0, b1);
                    MMA16816(C1[8], a1, b0, b1);
                }
            }
        }

        if (more2) {
            STS_A(s2);
            CP_WAIT1();
        } else {
            CP_WAIT0();
        }
        __syncthreads();
    }

    // ---- epilogue: fp32 partials ----
    {
        const int jmax = (ng == 0) ? 9 : 8;
        const int rowb = r0 + m0 + (lane >> 2);
        const int col0 = n0 + (lane & 3) * 2;
        float* base = &part_buf[(size_t)split * N_NODES * NCOLS];
        for (int j = 0; j < jmax; j++) {
            const int col = col0 + j * 8;
            *reinterpret_cast<float2*>(&base[(size_t)rowb * NCOLS + col]) =
                make_float2(C0[j][0], C0[j][1]);
            *reinterpret_cast<float2*>(&base[(size_t)(rowb + 8) * NCOLS + col]) =
                make_float2(C0[j][2], C0[j][3]);
            *reinterpret_cast<float2*>(&base[(size_t)(rowb + 16) * NCOLS + col]) =
                make_float2(C1[j][0], C1[j][1]);
            *reinterpret_cast<float2*>(&base[(size_t)(rowb + 24) * NCOLS + col]) =
                make_float2(C1[j][2], C1[j][3]);
        }
    }

    // ---- fused finalize: last split-CTA per tile combines partials ----
    __threadfence();
    __syncthreads();
    if (t == 0)
        s_last = (atomicAdd(&tile_cnt[tile], 1) == SPLITS - 1);
    __syncthreads();
    if (s_last) {
        __threadfence();   // acquire: make peer partials visible
        const int row = r0 + (t >> 1);
        const int ch  = (t & 1) * 64;
        float den = 0.0f;
        #pragma unroll
        for (int s = 0; s < SPLITS; s++)
            den += part_buf[((size_t)s * N_NODES + row) * NCOLS + 128];
        const float inv = 1.0f / den;
        #pragma unroll
        for (int q = 0; q < 16; q++) {
            float4 acc4 = make_float4(0.f, 0.f, 0.f, 0.f);
            #pragma unroll
            for (int s = 0; s < SPLITS; s++) {
                float4 v = *reinterpret_cast<const float4*>(
                    &part_buf[((size_t)s * N_NODES + row) * NCOLS + ch + 4 * q]);
                acc4.x += v.x; acc4.y += v.y; acc4.z += v.z; acc4.w += v.w;
            }
            float4 o;
            o.x = fmaxf(acc4.x * inv, 0.0f);
            o.y = fmaxf(acc4.y * inv, 0.0f);
            o.z = fmaxf(acc4.z * inv, 0.0f);
            o.w = fmaxf(acc4.w * inv, 0.0f);
            *reinterpret_cast<float4*>(&out[(size_t)row * OUT_DIM + ch + 4 * q]) = o;
        }
        if (t == 0) tile_cnt[tile] = 0;   // self-reset for next graph replay
    }
}

// ---------------------------------------------------------------------------
extern "C" void kernel_launch(void* const* d_in, const int* in_sizes, int n_in,
                              void* d_out, int out_size)
{
    const float* X   = (const float*)d_in[0];
    const float* A   = (const float*)d_in[1];
    const float* W   = (const float*)d_in[2];
    const float* a_w = (const float*)d_in[3];
    float* out = (float*)d_out;

    cudaFuncSetAttribute(gat_phase2,
                         cudaFuncAttributeMaxDynamicSharedMemorySize, PH2_SMEM);

    gat_phase1<<<N_NODES / 64, 256>>>(X, W, a_w);
    gat_phase2<<<64 * SPLITS, 256, PH2_SMEM>>>(A, out);
}

// round 16
// speedup vs baseline: 1.1301x; 1.0283x over previous
#include <cuda_runtime.h>
#include <cuda_fp16.h>
#include <cstdint>

#define N_NODES 8192
#define IN_DIM  256
#define OUT_DIM 128
#define NCOLS   144     // 128 out cols + g col (idx 128) + 15 pad
#define CH_K    32      // K per chunk (fp16), 64B rows
#define SPLITS  4

// ---------------- device scratch (zero-initialized at module load) ---------
__device__ __align__(16) __half Pt_f16[NCOLS * N_NODES];      // [n][k], rows>128 stay 0
__device__ __align__(16) float part_buf[SPLITS * N_NODES * NCOLS];
__device__ int tile_cnt[64];                                   // self-resetting

// ---------------- helpers ---------------------------------------------------
__device__ __forceinline__ uint32_t smem_u32(const void* p) {
    uint32_t a;
    asm("{ .reg .u64 t; cvta.to.shared.u64 t, %1; cvt.u32.u64 %0, t; }"
        : "=r"(a) : "l"(p));
    return a;
}
// XOR-swizzled byte offset inside a [rows][32 halves] tile (64B rows)
__device__ __forceinline__ uint32_t swz(int row, int chunk) {
    return (uint32_t)(row * 64 + ((chunk ^ ((row >> 1) & 3)) << 4));
}

#define LDSM_X4(r, addr) \
    asm volatile("ldmatrix.sync.aligned.m8n8.x4.shared.b16 {%0,%1,%2,%3}, [%4];" \
        : "=r"((r)[0]), "=r"((r)[1]), "=r"((r)[2]), "=r"((r)[3]) : "r"(addr))
#define LDSM_X2(r0, r1, addr) \
    asm volatile("ldmatrix.sync.aligned.m8n8.x2.shared.b16 {%0,%1}, [%2];" \
        : "=r"(r0), "=r"(r1) : "r"(addr))
#define MMA16816(c, a, b0, b1) \
    asm volatile("mma.sync.aligned.m16n8k16.row.col.f32.f16.f16.f32 " \
        "{%0,%1,%2,%3},{%4,%5,%6,%7},{%8,%9},{%0,%1,%2,%3};" \
        : "+f"((c)[0]), "+f"((c)[1]), "+f"((c)[2]), "+f"((c)[3]) \
        : "r"((a)[0]), "r"((a)[1]), "r"((a)[2]), "r"((a)[3]), "r"(b0), "r"(b1))
#define CP_ASYNC16(daddr, gptr) \
    asm volatile("cp.async.cg.shared.global [%0], [%1], 16;" \
        :: "r"(daddr), "l"(gptr) : "memory")
#define CP_COMMIT() asm volatile("cp.async.commit_group;" ::: "memory")
#define CP_WAIT0()  asm volatile("cp.async.wait_group 0;" ::: "memory")
#define CP_WAIT1()  asm volatile("cp.async.wait_group 1;" ::: "memory")

// ---------------------------------------------------------------------------
// Phase 1 (R15-measured ~25us: 4x8 tile + double-buffered k0 loop):
// Wh = X @ W^T, e = relu(Wh)@a_w, g = exp(e) (no max shift needed in fp16).
// Writes Pt_f16[c][node] = fp16(g*Wh[node][c]), row 128 = g.
// 128 blocks x 64 nodes, 256 threads (16tx x 16ty), tile 4 rows x 8 cols.
// ---------------------------------------------------------------------------
__global__ __launch_bounds__(256)
void gat_phase1(const float* __restrict__ X,
                const float* __restrict__ W,
                const float* __restrict__ a_w)
{
    // [Xs0 8704][Xs1 8704][Ws0 16896][Ws1 16896] = 51200 B
    __shared__ __align__(16) unsigned char sraw[51200];
    __shared__ float aw_s[OUT_DIM];

    const int t  = threadIdx.x;
    const int tx = t & 15;
    const int ty = t >> 4;
    const int node0 = blockIdx.x * 64;

    if (t < OUT_DIM) aw_s[t] = a_w[t];

    float acc[4][8];
    #pragma unroll
    for (int r = 0; r < 4; r++)
        #pragma unroll
        for (int j = 0; j < 8; j++) acc[r][j] = 0.0f;

    float4 xv[2], wv[4];
    const int xrow = t >> 2, xq = t & 3;
    const int wq = t & 7, wcb = t >> 3;

    auto LDGX = [&](int k0) {
        #pragma unroll
        for (int it = 0; it < 2; it++) {
            const int f4 = xq + 4 * it;
            xv[it] = *reinterpret_cast<const float4*>(
                &X[(node0 + xrow) * IN_DIM + k0 + 4 * f4]);
        }
    };
    auto LDGW = [&](int k0) {
        #pragma unroll
        for (int it = 0; it < 4; it++) {
            const int c = wcb + 32 * it;
            wv[it] = *reinterpret_cast<const float4*>(&W[c * IN_DIM + k0 + 4 * wq]);
        }
    };
    auto STSX = [&](int b) {
        float* Xb = (float*)(sraw + b * 8704);
        #pragma unroll
        for (int it = 0; it < 2; it++) {
            const int f4 = xq + 4 * it;
            Xb[(4*f4+0)*68 + xrow] = xv[it].x; Xb[(4*f4+1)*68 + xrow] = xv[it].y;
            Xb[(4*f4+2)*68 + xrow] = xv[it].z; Xb[(4*f4+3)*68 + xrow] = xv[it].w;
        }
    };
    auto STSW = [&](int b) {
        float* Wb = (float*)(sraw + 17408 + b * 16896);
        #pragma unroll
        for (int it = 0; it < 4; it++) {
            const int c = wcb + 32 * it;
            Wb[(4*wq+0)*132 + c] = wv[it].x; Wb[(4*wq+1)*132 + c] = wv[it].y;
            Wb[(4*wq+2)*132 + c] = wv[it].z; Wb[(4*wq+3)*132 + c] = wv[it].w;
        }
    };

    LDGX(0); LDGW(0); STSX(0); STSW(0);
    __syncthreads();

    for (int i = 0; i < 8; i++) {
        const int b = i & 1;
        if (i < 7) { LDGX(32 * (i + 1)); LDGW(32 * (i + 1)); }

        const float* Xb = (const float*)(sraw + b * 8704);
        const float* Wb = (const float*)(sraw + 17408 + b * 16896);
        #pragma unroll
        for (int k = 0; k < 32; k++) {
            float4 av = *reinterpret_cast<const float4*>(&Xb[k * 68 + 4 * ty]);
            float4 b0 = *reinterpret_cast<const float4*>(&Wb[k * 132 + 8 * tx]);
            float4 b1 = *reinterpret_cast<const float4*>(&Wb[k * 132 + 8 * tx + 4]);
            float a4[4] = {av.x, av.y, av.z, av.w};
            float bb[8] = {b0.x, b0.y, b0.z, b0.w, b1.x, b1.y, b1.z, b1.w};
            #pragma unroll
            for (int r = 0; r < 4; r++)
                #pragma unroll
                for (int j = 0; j < 8; j++)
                    acc[r][j] = fmaf(a4[r], bb[j], acc[r][j]);
        }
        if (i < 7) { STSX(b ^ 1); STSW(b ^ 1); }
        __syncthreads();
    }

    // g per row (reduce e over the 16 tx lanes; warp = 16 tx x 2 ty)
    float g[4];
    #pragma unroll
    for (int r = 0; r < 4; r++) {
        float ep = 0.0f;
        #pragma unroll
        for (int j = 0; j < 8; j++)
            ep = fmaf(fmaxf(acc[r][j], 0.0f), aw_s[8 * tx + j], ep);
        #pragma unroll
        for (int m = 8; m >= 1; m >>= 1)
            ep += __shfl_xor_sync(0xffffffffu, ep, m, 16);
        g[r] = expf(ep);
    }

    // transpose + fp16 through smem staging [129][72] (144B rows, 8B-aligned)
    __half* th = (__half*)sraw;
    #pragma unroll
    for (int j = 0; j < 8; j++) {
        const int c = 8 * tx + j;
        __half2 o0 = __floats2half2_rn(g[0] * acc[0][j], g[1] * acc[1][j]);
        __half2 o1 = __floats2half2_rn(g[2] * acc[2][j], g[3] * acc[3][j]);
        uint2 u;
        u.x = *reinterpret_cast<unsigned*>(&o0);
        u.y = *reinterpret_cast<unsigned*>(&o1);
        *reinterpret_cast<uint2*>(&th[c * 72 + 4 * ty]) = u;
    }
    if (tx == 0) {
        __half2 o0 = __floats2half2_rn(g[0], g[1]);
        __half2 o1 = __floats2half2_rn(g[2], g[3]);
        uint2 u;
        u.x = *reinterpret_cast<unsigned*>(&o0);
        u.y = *reinterpret_cast<unsigned*>(&o1);
        *reinterpret_cast<uint2*>(&th[128 * 72 + 4 * ty]) = u;
    }
    __syncthreads();
    {   // write out: 129 rows x 64 nodes (128B per row, one warp per row)
        const int wid = t >> 5, lid = t & 31;
        for (int c = wid; c < 129; c += 8) {
            unsigned v = *reinterpret_cast<unsigned*>(&th[c * 72 + 2 * lid]);
            *reinterpret_cast<unsigned*>(
                &Pt_f16[(size_t)c * N_NODES + node0 + 2 * lid]) = v;
        }
    }
}

// ---------------------------------------------------------------------------
// Phase 2 (EXACT R13 structure, measured 116.0/114.8us): fp16 HMMA GEMM +
// fused cross-split finalize. CTA: M=128, N=144, K-chunk 32; 256 threads =
// 8 warps (4m x 2n, m32 x n72). 3-stage pipeline, 256 CTAs, 2 CTAs/SM.
// ---------------------------------------------------------------------------
#define STG_BYTES 17408     // A 8192 + B 9216
#define B_OFF     8192
#define PH2_SMEM  (3 * STG_BYTES)

__global__ __launch_bounds__(256, 2)
void gat_phase2(const float* __restrict__ A, float* __restrict__ out)
{
    extern __shared__ unsigned char sm[];
    const uint32_t sbase0 = smem_u32(sm);
    __shared__ int s_last;

    const int t     = threadIdx.x;
    const int lane  = t & 31;
    const int wid   = t >> 5;
    const int tile  = blockIdx.x & 63;
    const int split = blockIdx.x >> 6;
    const int r0    = tile * 128;
    const int kbase = split * (N_NODES / SPLITS);
    const int NCH   = (N_NODES / SPLITS) / CH_K;   // 64

    const int m0 = (wid & 3) * 32;
    const int n0 = (wid >> 2) * 72;

    float C0[9][4], C1[9][4];
    #pragma unroll
    for (int j = 0; j < 9; j++)
        #pragma unroll
        for (int q = 0; q < 4; q++) { C0[j][q] = 0.0f; C1[j][q] = 0.0f; }

    float4 av[4];
    const int ar = t >> 1;
    const int ac = t & 1;

    auto LDG_A = [&](int i) {
        const float4* src = reinterpret_cast<const float4*>(
            &A[(size_t)(r0 + ar) * N_NODES + kbase + i * CH_K + ac * 16]);
        av[0] = src[0]; av[1] = src[1]; av[2] = src[2]; av[3] = src[3];
    };
    auto STS_A = [&](int stg) {
        #pragma unroll
        for (int h = 0; h < 2; h++) {
            __half2 p0 = __floats2half2_rn(av[2*h].x, av[2*h].y);
            __half2 p1 = __floats2half2_rn(av[2*h].z, av[2*h].w);
            __half2 p2 = __floats2half2_rn(av[2*h+1].x, av[2*h+1].y);
            __half2 p3 = __floats2half2_rn(av[2*h+1].z, av[2*h+1].w);
            uint4 u;
            u.x = *reinterpret_cast<unsigned*>(&p0);
            u.y = *reinterpret_cast<unsigned*>(&p1);
            u.z = *reinterpret_cast<unsigned*>(&p2);
            u.w = *reinterpret_cast<unsigned*>(&p3);
            *reinterpret_cast<uint4*>(sm + stg * STG_BYTES + swz(ar, ac * 2 + h)) = u;
        }
    };
    auto LOAD_B = [&](int i, int stg) {
        const uint32_t db = sbase0 + stg * STG_BYTES + B_OFF;
        #pragma unroll
        for (int it = 0; it < 3; it++) {
            int idx = t + it * 256;
            if (idx < 576) {
                int n = idx >> 2, c = idx & 3;
                const __half* g = Pt_f16 + (size_t)n * N_NODES
                                + kbase + i * CH_K + c * 8;
                CP_ASYNC16(db + swz(n, c), g);
            }
        }
    };

    // ---- prologue ----
    LDG_A(0); STS_A(0); LOAD_B(0, 0); CP_COMMIT();
    LDG_A(1); STS_A(1); LOAD_B(1, 1); CP_COMMIT();
    CP_WAIT1();
    __syncthreads();

    // ---- main loop ----
    for (int i = 0; i < NCH; i++) {
        const int s = i % 3;
        const bool more2 = (i + 2 < NCH);
        const int s2 = (i + 2) % 3;
        if (more2) {
            LDG_A(i + 2);
            LOAD_B(i + 2, s2);
            CP_COMMIT();
        }

        {
            const uint32_t ab = sbase0 + s * STG_BYTES;
            const uint32_t bb = ab + B_OFF;
            #pragma unroll
            for (int h = 0; h < 2; h++) {
                uint32_t a0[4], a1[4];
                {
                    const int kc = 2 * h + (lane >> 4);
                    LDSM_X4(a0, ab + swz(m0 + (lane & 15), kc));
                    LDSM_X4(a1, ab + swz(m0 + 16 + (lane & 15), kc));
                }
                const int kcb = 2 * h + ((lane >> 3) & 1);
                #pragma unroll
                for (int jg = 0; jg < 4; jg++) {
                    int n = n0 + jg * 16 + ((lane >> 4) << 3) + (lane & 7);
                    uint32_t b[4];
                    LDSM_X4(b, bb + swz(n, kcb));
                    MMA16816(C0[2*jg],   a0, b[0], b[1]);
                    MMA16816(C0[2*jg+1], a0, b[2], b[3]);
                    MMA16816(C1[2*jg],   a1, b[0], b[1]);
                    MMA16816(C1[2*jg+1], a1, b[2], b[3]);
                }
                {
                    int n = n0 + 64 + (lane & 7);
                    uint32_t b0, b1;
                    LDSM_X2(b0, b1, bb + swz(n, kcb));
                    MMA16816(C0[8], a0, b0, b1);
                    MMA16816(C1[8], a1, b0, b1);
                }
            }
        }

        if (more2) {
            STS_A(s2);
            CP_WAIT1();
        } else {
            CP_WAIT0();
        }
        __syncthreads();
    }

    // ---- epilogue: fp32 partials ----
    {
        const int rowb = r0 + m0 + (lane >> 2);
        const int col0 = n0 + (lane & 3) * 2;
        float* base = &part_buf[(size_t)split * N_NODES * NCOLS];
        #pragma unroll
        for (int j = 0; j < 9; j++) {
            const int col = col0 + j * 8;
            *reinterpret_cast<float2*>(&base[(size_t)rowb * NCOLS + col]) =
                make_float2(C0[j][0], C0[j][1]);
            *reinterpret_cast<float2*>(&base[(size_t)(rowb + 8) * NCOLS + col]) =
                make_float2(C0[j][2], C0[j][3]);
            *reinterpret_cast<float2*>(&base[(size_t)(rowb + 16) * NCOLS + col]) =
                make_float2(C1[j][0], C1[j][1]);
            *reinterpret_cast<float2*>(&base[(size_t)(rowb + 24) * NCOLS + col]) =
                make_float2(C1[j][2], C1[j][3]);
        }
    }

    // ---- fused finalize: last split-CTA per tile combines partials ----
    __threadfence();
    __syncthreads();
    if (t == 0)
        s_last = (atomicAdd(&tile_cnt[tile], 1) == SPLITS - 1);
    __syncthreads();
    if (s_last) {
        __threadfence();   // acquire: make peer partials visible
        const int row = r0 + (t >> 1);
        const int ch  = (t & 1) * 64;
        float den = 0.0f;
        #pragma unroll
        for (int s = 0; s < SPLITS; s++)
            den += part_buf[((size_t)s * N_NODES + row) * NCOLS + 128];
        const float inv = 1.0f / den;
        #pragma unroll
        for (int q = 0; q < 16; q++) {
            float4 acc4 = make_float4(0.f, 0.f, 0.f, 0.f);
            #pragma unroll
            for (int s = 0; s < SPLITS; s++) {
                float4 v = *reinterpret_cast<const float4*>(
                    &part_buf[((size_t)s * N_NODES + row) * NCOLS + ch + 4 * q]);
                acc4.x += v.x; acc4.y += v.y; acc4.z += v.z; acc4.w += v.w;
            }
            float4 o;
            o.x = fmaxf(acc4.x * inv, 0.0f);
            o.y = fmaxf(acc4.y * inv, 0.0f);
            o.z = fmaxf(acc4.z * inv, 0.0f);
            o.w = fmaxf(acc4.w * inv, 0.0f);
            *reinterpret_cast<float4*>(&out[(size_t)row * OUT_DIM + ch + 4 * q]) = o;
        }
        if (t == 0) tile_cnt[tile] = 0;   // self-reset for next graph replay
    }
}

// ---------------------------------------------------------------------------
extern "C" void kernel_launch(void* const* d_in, const int* in_sizes, int n_in,
                              void* d_out, int out_size)
{
    const float* X   = (const float*)d_in[0];
    const float* A   = (const float*)d_in[1];
    const float* W   = (const float*)d_in[2];
    const float* a_w = (const float*)d_in[3];
    float* out = (float*)d_out;

    cudaFuncSetAttribute(gat_phase2,
                         cudaFuncAttributeMaxDynamicSharedMemorySize, PH2_SMEM);

    gat_phase1<<<N_NODES / 64, 256>>>(X, W, a_w);
    gat_phase2<<<64 * SPLITS, 256, PH2_SMEM>>>(A, out);
}